// round 4
// baseline (speedup 1.0000x reference)
#include <cuda_runtime.h>
#include <cstdint>
#include <cstddef>

// Adaptive separable convolution (SepConv), sm_103a.
// out[b,c,y,w] = sum_i sum_j inp[b,c,y+i,w+j] * V[b,i,y,w] * Hz[b,j,y,w]
//
// Round-4 design:
//  * FFMA2 (fma.rn.f32x2) packed math, 4 adjacent output pixels per thread.
//  * One channel per CTA (grid z = B*C), TILE 128x4, 128-thread CTAs.
//  * Tap pairs m = 0..27 split into 3 uniform phases of 8 pairs + tail of 4,
//    weight array w[4][8] REUSED across phases -> ~118 live regs -> 4 CTAs/SM.
//  * ld.shared.v2.u64: LDS.128 directly into 64-bit pairs (no pack MOVs).

#define KF   51
#define BB   2
#define CC   3
#define HH   256
#define WW   256
#define HW   (HH * WW)            // 65536
#define IN_H (HH + KF - 1)        // 306
#define IN_W (WW + KF - 1)        // 306

#define TILE_W 128
#define TILE_H 4
#define PATCH_H (TILE_H + KF - 1) // 54
#define PATCH_W (TILE_W + KF - 1) // 178
#define PATCH_WP 180              // padded row: 720B (45*16), cols 178..179 zeroed
#define ROW_BYTES (PATCH_WP * 4)  // 720

#define NTHREADS 128              // 4 warps, one output row each

__device__ __forceinline__ uint64_t pk2(float lo, float hi) {
    uint64_t r;
    asm("mov.b64 %0, {%1,%2};" : "=l"(r) : "f"(lo), "f"(hi));
    return r;
}
__device__ __forceinline__ void ffma2(uint64_t& acc, uint64_t a, uint64_t b) {
    asm("fma.rn.f32x2 %0, %1, %2, %0;" : "+l"(acc) : "l"(a), "l"(b));
}
__device__ __forceinline__ float hadd2(uint64_t p) {
    float lo, hi;
    asm("mov.b64 {%0,%1}, %2;" : "=f"(lo), "=f"(hi) : "l"(p));
    return lo + hi;
}
__device__ __forceinline__ void lds128(uint64_t& q0, uint64_t& q1, uint32_t saddr) {
    asm("ld.shared.v2.u64 {%0,%1}, [%2];" : "=l"(q0), "=l"(q1) : "r"(saddr));
}

__global__ void __launch_bounds__(NTHREADS, 4)
sepconv_kernel(const float* __restrict__ inp,
               const float* __restrict__ ver,
               const float* __restrict__ hor,
               float* __restrict__ out)
{
    __shared__ __align__(16) float sm[PATCH_H][PATCH_WP];

    const int bx = blockIdx.x;            // 0..1   tile col
    const int by = blockIdx.y;            // 0..63  tile row
    const int bc = blockIdx.z;            // 0..5   (b, c) fused
    const int b  = bc / CC;
    const int c  = bc - b * CC;
    const int x0 = bx * TILE_W;
    const int y0 = by * TILE_H;

    const int tid  = threadIdx.x;
    const int lane = tid & 31;
    const int wy   = tid >> 5;            // warp id == row within tile
    const int y    = y0 + wy;             // output row
    const int w0   = x0 + 4 * lane;       // first of 4 output cols

    const float* Hb = hor + ((size_t)b * KF * HW) + (size_t)y * WW + w0;
    const float* Vb = ver + ((size_t)b * KF * HW) + (size_t)y * WW + w0;

    // ---- single patch fill for this CTA's channel (+ zero pad cols) ----
    {
        const float* src = inp + ((size_t)(b * CC + c) * IN_H + y0) * IN_W + x0;
        for (int t = tid; t < PATCH_H * (PATCH_W / 2); t += NTHREADS) {
            int r  = t / (PATCH_W / 2);
            int c2 = t - r * (PATCH_W / 2);
            float2 v = *(const float2*)(src + (size_t)r * IN_W + 2 * c2);
            *(float2*)(&sm[r][2 * c2]) = v;
        }
        if (tid < PATCH_H) {              // zero pad so m=27 pair is harmless
            sm[tid][PATCH_W]     = 0.0f;
            sm[tid][PATCH_W + 1] = 0.0f;
        }
    }
    __syncthreads();

    // per-thread shared base address: row wy(+i), float col 4*lane
    const uint32_t smbase = (uint32_t)__cvta_generic_to_shared(&sm[0][0])
                          + (uint32_t)(wy * ROW_BYTES) + (uint32_t)(lane * 16);

    float res0 = 0.0f, res1 = 0.0f, res2 = 0.0f, res3 = 0.0f;

    // ============ 3 uniform phases: pairs m = 8*ph .. 8*ph+7 ============
#pragma unroll 1
    for (int ph = 0; ph < 3; ++ph) {
        // packed weights: w[p][r] = (Hz[p, 2m-p], Hz[p, 2m+1-p]), m = 8ph+r
        uint64_t w[4][8];
#pragma unroll
        for (int p = 0; p < 4; ++p) {
#pragma unroll
            for (int r = 0; r < 8; ++r) {
                int m  = 8 * ph + r;
                int j0 = 2 * m - p;
                int j1 = j0 + 1;
                float f0 = (j0 >= 0 && j0 < KF) ? Hb[(size_t)j0 * HW + p] : 0.0f;
                float f1 = (j1 >= 0 && j1 < KF) ? Hb[(size_t)j1 * HW + p] : 0.0f;
                w[p][r] = pk2(f0, f1);
            }
        }

        uint64_t o0 = 0, o1 = 0, o2 = 0, o3 = 0;
        const float* Vp = Vb;
        uint32_t srow = smbase + (uint32_t)(ph * 64);   // float 16*ph

#pragma unroll 1
        for (int i = 0; i < KF; ++i) {
            float4 v4 = *(const float4*)Vp;
            Vp += HW;

            uint64_t q[8];
#pragma unroll
            for (int t = 0; t < 4; ++t)
                lds128(q[2 * t], q[2 * t + 1], srow + 16 * t);
            srow += ROW_BYTES;

            uint64_t a0 = 0, a1 = 0, a2 = 0, a3 = 0;
#pragma unroll
            for (int r = 0; r < 8; ++r) {
                ffma2(a0, w[0][r], q[r]);
                ffma2(a1, w[1][r], q[r]);
                ffma2(a2, w[2][r], q[r]);
                ffma2(a3, w[3][r], q[r]);
            }
            ffma2(o0, pk2(v4.x, v4.x), a0);
            ffma2(o1, pk2(v4.y, v4.y), a1);
            ffma2(o2, pk2(v4.z, v4.z), a2);
            ffma2(o3, pk2(v4.w, v4.w), a3);
        }
        res0 += hadd2(o0);
        res1 += hadd2(o1);
        res2 += hadd2(o2);
        res3 += hadd2(o3);
    }

    // ============ tail phase: pairs m = 24..27 (m=27 weights are all pad) ====
    {
        uint64_t w[4][4];
#pragma unroll
        for (int p = 0; p < 4; ++p) {
#pragma unroll
            for (int r = 0; r < 4; ++r) {
                int m  = 24 + r;
                int j0 = 2 * m - p;
                int j1 = j0 + 1;
                float f0 = (j0 >= 0 && j0 < KF) ? Hb[(size_t)j0 * HW + p] : 0.0f;
                float f1 = (j1 >= 0 && j1 < KF) ? Hb[(size_t)j1 * HW + p] : 0.0f;
                w[p][r] = pk2(f0, f1);
            }
        }

        uint64_t o0 = 0, o1 = 0, o2 = 0, o3 = 0;
        const float* Vp = Vb;
        uint32_t srow = smbase + 192;                   // float 48

#pragma unroll 1
        for (int i = 0; i < KF; ++i) {
            float4 v4 = *(const float4*)Vp;
            Vp += HW;

            uint64_t q[4];
            lds128(q[0], q[1], srow);
            lds128(q[2], q[3], srow + 16);
            srow += ROW_BYTES;

            uint64_t a0 = 0, a1 = 0, a2 = 0, a3 = 0;
#pragma unroll
            for (int r = 0; r < 4; ++r) {
                ffma2(a0, w[0][r], q[r]);
                ffma2(a1, w[1][r], q[r]);
                ffma2(a2, w[2][r], q[r]);
                ffma2(a3, w[3][r], q[r]);
            }
            ffma2(o0, pk2(v4.x, v4.x), a0);
            ffma2(o1, pk2(v4.y, v4.y), a1);
            ffma2(o2, pk2(v4.z, v4.z), a2);
            ffma2(o3, pk2(v4.w, v4.w), a3);
        }
        res0 += hadd2(o0);
        res1 += hadd2(o1);
        res2 += hadd2(o2);
        res3 += hadd2(o3);
    }

    // ---- write out ----
    float* o = out + ((size_t)(b * CC + c) * HH + y) * WW + w0;
    *(float4*)o = make_float4(res0, res1, res2, res3);
}

extern "C" void kernel_launch(void* const* d_in, const int* in_sizes, int n_in,
                              void* d_out, int out_size)
{
    (void)in_sizes; (void)n_in; (void)out_size;
    const float* inp = (const float*)d_in[0];   // [B, C, 306, 306]
    const float* ver = (const float*)d_in[1];   // [B, 51, 256, 256]
    const float* hor = (const float*)d_in[2];   // [B, 51, 256, 256]
    float*       out = (float*)d_out;           // [B, C, 256, 256]

    dim3 grid(WW / TILE_W, HH / TILE_H, BB * CC);   // (2, 64, 6) = 768 blocks
    dim3 block(NTHREADS);
    sepconv_kernel<<<grid, block>>>(inp, ver, hor, out);
}

// round 5
// speedup vs baseline: 1.2498x; 1.2498x over previous
#include <cuda_runtime.h>
#include <cstdint>
#include <cstddef>

// Adaptive separable convolution (SepConv), sm_103a.
// out[b,c,y,w] = sum_i sum_j inp[b,c,y+i,w+j] * V[b,i,y,w] * Hz[b,j,y,w]
//
// Round-5 design = Round-3 (best: 70.6us) + V software pipelining:
//  * FFMA2 (fma.rn.f32x2) packed math, 4 adjacent output pixels per thread.
//  * One channel per CTA (grid z = B*C), TILE 128x4, 128-thread CTAs, 3 CTAs/SM.
//  * 2 weight phases (pairs 0..13 / 14..26), ~108 live weight regs per phase.
//  * NEW: V[i+1] is prefetched (clamped pointer, branchless) before the FFMA
//    block of iteration i -> the ~234-577cyc L2 latency of the per-pixel
//    vertical weights overlaps compute instead of serializing every iteration.

#define KF   51
#define BB   2
#define CC   3
#define HH   256
#define WW   256
#define HW   (HH * WW)            // 65536
#define IN_H (HH + KF - 1)        // 306
#define IN_W (WW + KF - 1)        // 306

#define TILE_W 128
#define TILE_H 4
#define PATCH_H (TILE_H + KF - 1) // 54
#define PATCH_W (TILE_W + KF - 1) // 178
#define PATCH_WP 180              // padded row: 720B, 16B-aligned

#define NTHREADS 128              // 4 warps, one output row each

__device__ __forceinline__ uint64_t pk2(float lo, float hi) {
    uint64_t r;
    asm("mov.b64 %0, {%1,%2};" : "=l"(r) : "f"(lo), "f"(hi));
    return r;
}
__device__ __forceinline__ void ffma2(uint64_t& acc, uint64_t a, uint64_t b) {
    asm("fma.rn.f32x2 %0, %1, %2, %0;" : "+l"(acc) : "l"(a), "l"(b));
}
__device__ __forceinline__ float hadd2(uint64_t p) {
    float lo, hi;
    asm("mov.b64 {%0,%1}, %2;" : "=f"(lo), "=f"(hi) : "l"(p));
    return lo + hi;
}

__global__ void __launch_bounds__(NTHREADS, 3)
sepconv_kernel(const float* __restrict__ inp,
               const float* __restrict__ ver,
               const float* __restrict__ hor,
               float* __restrict__ out)
{
    __shared__ __align__(16) float sm[PATCH_H][PATCH_WP];

    const int bx = blockIdx.x;            // 0..1   tile col
    const int by = blockIdx.y;            // 0..63  tile row
    const int bc = blockIdx.z;            // 0..5   (b, c) fused
    const int b  = bc / CC;
    const int c  = bc - b * CC;
    const int x0 = bx * TILE_W;
    const int y0 = by * TILE_H;

    const int tid  = threadIdx.x;
    const int lane = tid & 31;
    const int wy   = tid >> 5;            // warp id == row within tile
    const int y    = y0 + wy;             // output row
    const int w0   = x0 + 4 * lane;       // first of 4 output cols

    const float* Hb = hor + ((size_t)b * KF * HW) + (size_t)y * WW + w0;
    const float* Vb = ver + ((size_t)b * KF * HW) + (size_t)y * WW + w0;

    // horizontal weight fetch for pixel p, tap j (compile-time predicated pad)
    auto hz = [&](int p, int j) -> float {
        return (j >= 0 && j < KF) ? Hb[(size_t)j * HW + p] : 0.0f;
    };

    // ---- single patch fill for this CTA's channel ----
    {
        const float* src = inp + ((size_t)(b * CC + c) * IN_H + y0) * IN_W + x0;
        for (int t = tid; t < PATCH_H * (PATCH_W / 2); t += NTHREADS) {
            int r  = t / (PATCH_W / 2);
            int c2 = t - r * (PATCH_W / 2);
            float2 v = *(const float2*)(src + (size_t)r * IN_W + 2 * c2);
            *(float2*)(&sm[r][2 * c2]) = v;
        }
    }

    float res0, res1, res2, res3;

    // ================= PHASE A : pairs k = 0..13 (taps j <= 27) =============
    {
        uint64_t wa0[14], wa1[14], wa2[13], wa3[13];
#pragma unroll
        for (int k = 0; k < 14; ++k) {
            wa0[k] = pk2(hz(0, 2 * k),     hz(0, 2 * k + 1));
            wa1[k] = pk2(hz(1, 2 * k - 1), hz(1, 2 * k));
        }
#pragma unroll
        for (int k = 1; k < 14; ++k) {
            wa2[k - 1] = pk2(hz(2, 2 * k - 2), hz(2, 2 * k - 1));
            wa3[k - 1] = pk2(hz(3, 2 * k - 3), hz(3, 2 * k - 2));
        }

        __syncthreads();   // patch visible before compute

        uint64_t o0 = 0, o1 = 0, o2 = 0, o3 = 0;
        float4 v4 = *(const float4*)Vb;       // prologue load for i = 0
#pragma unroll 1
        for (int i = 0; i < KF; ++i) {
            // prefetch V for next iteration (clamped: last iter re-reads i=50)
            const float* Vn = Vb + (size_t)((i + 1 < KF) ? (i + 1) : i) * HW;
            float4 vnext = *(const float4*)Vn;

            const float4* srow4 = (const float4*)(&sm[wy + i][0]);
            uint64_t a0 = 0, a1 = 0, a2 = 0, a3 = 0;
#pragma unroll
            for (int t = 0; t < 7; ++t) {
                float4 s4 = srow4[lane + t];
                uint64_t q0 = pk2(s4.x, s4.y);   // pair k = 2t
                uint64_t q1 = pk2(s4.z, s4.w);   // pair k = 2t+1
                int k0 = 2 * t, k1 = 2 * t + 1;
                ffma2(a0, wa0[k0], q0);
                ffma2(a1, wa1[k0], q0);
                if (k0 >= 1) { ffma2(a2, wa2[k0 - 1], q0); ffma2(a3, wa3[k0 - 1], q0); }
                ffma2(a0, wa0[k1], q1);
                ffma2(a1, wa1[k1], q1);
                ffma2(a2, wa2[k1 - 1], q1);
                ffma2(a3, wa3[k1 - 1], q1);
            }
            ffma2(o0, pk2(v4.x, v4.x), a0);
            ffma2(o1, pk2(v4.y, v4.y), a1);
            ffma2(o2, pk2(v4.z, v4.z), a2);
            ffma2(o3, pk2(v4.w, v4.w), a3);
            v4 = vnext;
        }
        res0 = hadd2(o0);
        res1 = hadd2(o1);
        res2 = hadd2(o2);
        res3 = hadd2(o3);
    }

    __syncthreads();   // fence: keep phase-B weight loads below phase A

    // ================= PHASE B : pairs k = 14..26 (taps j >= 25) ============
    {
        uint64_t wb0[12], wb1[12], wb2[13], wb3[13];
#pragma unroll
        for (int k = 14; k < 26; ++k) {
            wb0[k - 14] = pk2(hz(0, 2 * k),     hz(0, 2 * k + 1)); // k=25 -> pad
            wb1[k - 14] = pk2(hz(1, 2 * k - 1), hz(1, 2 * k));
        }
#pragma unroll
        for (int k = 14; k < 27; ++k) {
            wb2[k - 14] = pk2(hz(2, 2 * k - 2), hz(2, 2 * k - 1)); // k=26 -> pad
            wb3[k - 14] = pk2(hz(3, 2 * k - 3), hz(3, 2 * k - 2));
        }

        uint64_t o0 = 0, o1 = 0, o2 = 0, o3 = 0;
        float4 v4 = *(const float4*)Vb;       // prologue load for i = 0
#pragma unroll 1
        for (int i = 0; i < KF; ++i) {
            const float* Vn = Vb + (size_t)((i + 1 < KF) ? (i + 1) : i) * HW;
            float4 vnext = *(const float4*)Vn;

            const float* srow = &sm[wy + i][0];
            const float4* srow4 = (const float4*)srow;
            uint64_t a0 = 0, a1 = 0, a2 = 0, a3 = 0;
#pragma unroll
            for (int t = 0; t < 6; ++t) {
                float4 s4 = srow4[lane + 7 + t];          // floats 28..51
                uint64_t q0 = pk2(s4.x, s4.y);            // pair k = 14+2t
                uint64_t q1 = pk2(s4.z, s4.w);            // pair k = 15+2t
                int k0 = 2 * t, k1 = 2 * t + 1;           // rel index
                ffma2(a0, wb0[k0], q0);
                ffma2(a1, wb1[k0], q0);
                ffma2(a2, wb2[k0], q0);
                ffma2(a3, wb3[k0], q0);
                ffma2(a0, wb0[k1], q1);
                ffma2(a1, wb1[k1], q1);
                ffma2(a2, wb2[k1], q1);
                ffma2(a3, wb3[k1], q1);
            }
            {   // tail pair k = 26 (floats 52,53): pixels 2,3 only
                float2 s2 = *(const float2*)(srow + 4 * lane + 52);
                uint64_t q = pk2(s2.x, s2.y);
                ffma2(a2, wb2[12], q);
                ffma2(a3, wb3[12], q);
            }
            ffma2(o0, pk2(v4.x, v4.x), a0);
            ffma2(o1, pk2(v4.y, v4.y), a1);
            ffma2(o2, pk2(v4.z, v4.z), a2);
            ffma2(o3, pk2(v4.w, v4.w), a3);
            v4 = vnext;
        }
        res0 += hadd2(o0);
        res1 += hadd2(o1);
        res2 += hadd2(o2);
        res3 += hadd2(o3);
    }

    // ---- write out ----
    float* o = out + ((size_t)(b * CC + c) * HH + y) * WW + w0;
    *(float4*)o = make_float4(res0, res1, res2, res3);
}

extern "C" void kernel_launch(void* const* d_in, const int* in_sizes, int n_in,
                              void* d_out, int out_size)
{
    (void)in_sizes; (void)n_in; (void)out_size;
    const float* inp = (const float*)d_in[0];   // [B, C, 306, 306]
    const float* ver = (const float*)d_in[1];   // [B, 51, 256, 256]
    const float* hor = (const float*)d_in[2];   // [B, 51, 256, 256]
    float*       out = (float*)d_out;           // [B, C, 256, 256]

    dim3 grid(WW / TILE_W, HH / TILE_H, BB * CC);   // (2, 64, 6) = 768 blocks
    dim3 block(NTHREADS);
    sepconv_kernel<<<grid, block>>>(inp, ver, hor, out);
}